// round 14
// baseline (speedup 1.0000x reference)
#include <cuda_runtime.h>
#include <cstdint>

#define BATCH 512
#define SEQ   256
#define DIM   256
#define NEG_SLOPE 0.1f

// ------------------------------------------------------------------
// Scratch (device globals; no allocation inside kernel_launch)
// ------------------------------------------------------------------
__device__ float g_Wh[(size_t)BATCH * SEQ * DIM];   // 134 MB
__device__ float g_e[2 * BATCH * SEQ];              // e_l then e_r(+a_b)
__device__ float g_u[2 * DIM];                      // u_l, u_r = W1^T a_{l,r}
__device__ float g_c[2];                            // b1·a_l , b1·a_r + a_b

// ------------------------------------------------------------------
// K0: u_l[d] = sum_e W1[e,d]*a_w[e], u_r[d] = sum_e W1[e,d]*a_w[D+e]
//     c_l = b1·a_l, c_r = b1·a_r + a_b
// ------------------------------------------------------------------
__global__ void k0_prep(const float* __restrict__ W1, const float* __restrict__ b1,
                        const float* __restrict__ aw, const float* __restrict__ ab) {
    int d = threadIdx.x;  // 256 threads
    float ul = 0.f, ur = 0.f;
    for (int e = 0; e < DIM; ++e) {
        float w = W1[e * DIM + d];
        ul += w * aw[e];
        ur += w * aw[DIM + e];
    }
    g_u[d] = ul;
    g_u[DIM + d] = ur;

    __shared__ float s1[256], s2[256];
    s1[d] = b1[d] * aw[d];
    s2[d] = b1[d] * aw[DIM + d];
    __syncthreads();
    for (int off = 128; off > 0; off >>= 1) {
        if (d < off) { s1[d] += s1[d + off]; s2[d] += s2[d + off]; }
        __syncthreads();
    }
    if (d == 0) { g_c[0] = s1[0]; g_c[1] = s2[0] + ab[0]; }
}

// ------------------------------------------------------------------
// K2: e_l[row] = x[row,:]·u_l + c_l ; e_r[row] = x[row,:]·u_r + c_r
//     (warp per row, 8 rows per block)
// ------------------------------------------------------------------
__global__ void k2_e(const float* __restrict__ x) {
    __shared__ __align__(16) float su[2 * DIM];
    int t = threadIdx.x;  // 256
    su[t]       = g_u[t];
    su[t + 256] = g_u[t + 256];
    __syncthreads();

    int warp = t >> 5, lane = t & 31;
    size_t row = (size_t)blockIdx.x * 8 + warp;
    const float4* xr  = reinterpret_cast<const float4*>(x + row * 256);
    const float4* ul4 = reinterpret_cast<const float4*>(su);
    const float4* ur4 = reinterpret_cast<const float4*>(su + 256);

    float el = 0.f, er = 0.f;
#pragma unroll
    for (int k = 0; k < 2; ++k) {
        float4 v = xr[lane + 32 * k];
        float4 a = ul4[lane + 32 * k];
        float4 c = ur4[lane + 32 * k];
        el += v.x * a.x + v.y * a.y + v.z * a.z + v.w * a.w;
        er += v.x * c.x + v.y * c.y + v.z * c.z + v.w * c.w;
    }
#pragma unroll
    for (int o = 16; o > 0; o >>= 1) {
        el += __shfl_down_sync(0xffffffffu, el, o);
        er += __shfl_down_sync(0xffffffffu, er, o);
    }
    if (lane == 0) {
        g_e[row] = el + g_c[0];
        g_e[(size_t)BATCH * SEQ + row] = er + g_c[1];
    }
}

// ------------------------------------------------------------------
// K1: Wh = x @ W1^T + b1   (register-tiled SGEMM, 128x128 block tile,
//     8x8 microtile, K processed in 16-wide smem steps, W staged in
//     transposed 32-k chunks for conflict-free float4 LDS)
// ------------------------------------------------------------------
__global__ void __launch_bounds__(256, 2)
k1_gemm(const float* __restrict__ x, const float* __restrict__ W1,
        const float* __restrict__ b1) {
    __shared__ __align__(16) float Wt[32][132];  // [k_local][e_local]
    __shared__ __align__(16) float Xs[16][132];  // [k][m]

    const int t  = threadIdx.x;
    const int tx = t & 15;   // column group: cols tx*4..+3 and 64+tx*4..+3
    const int ty = t >> 4;   // row group:    rows ty*8..+7
    const int e0 = blockIdx.x * 128;
    const int m0 = blockIdx.y * 128;

    float acc[8][8];
#pragma unroll
    for (int r = 0; r < 8; ++r)
#pragma unroll
        for (int c = 0; c < 8; ++c) acc[r][c] = 0.f;

    const int we = t >> 1;   // 0..127: e row for W staging
    const int wp = t & 1;
    const int xm = t >> 1;   // 0..127: m row for X staging

    for (int step = 0; step < 16; ++step) {
        __syncthreads();
        if ((step & 1) == 0) {
            const int kc = step >> 1;  // 32-k chunk index
            const float* wsrc = W1 + (size_t)(e0 + we) * 256 + kc * 32;
#pragma unroll
            for (int q = 0; q < 4; ++q) {
                const int d0 = wp * 4 + q * 8;
                float4 v = *(const float4*)(wsrc + d0);
                Wt[d0 + 0][we] = v.x;
                Wt[d0 + 1][we] = v.y;
                Wt[d0 + 2][we] = v.z;
                Wt[d0 + 3][we] = v.w;
            }
        }
        {
            const float* xsrc = x + (size_t)(m0 + xm) * 256 + step * 16 + wp * 8;
            float4 v0 = *(const float4*)(xsrc);
            float4 v1 = *(const float4*)(xsrc + 4);
            const int kb = wp * 8;
            Xs[kb + 0][xm] = v0.x; Xs[kb + 1][xm] = v0.y;
            Xs[kb + 2][xm] = v0.z; Xs[kb + 3][xm] = v0.w;
            Xs[kb + 4][xm] = v1.x; Xs[kb + 5][xm] = v1.y;
            Xs[kb + 6][xm] = v1.z; Xs[kb + 7][xm] = v1.w;
        }
        __syncthreads();

        const int klb = (step & 1) * 16;
#pragma unroll
        for (int kk = 0; kk < 16; ++kk) {
            float4 a0 = *(const float4*)&Xs[kk][ty * 8];
            float4 a1 = *(const float4*)&Xs[kk][ty * 8 + 4];
            float4 w0 = *(const float4*)&Wt[klb + kk][tx * 4];
            float4 w1 = *(const float4*)&Wt[klb + kk][64 + tx * 4];
            float ar[8] = {a0.x, a0.y, a0.z, a0.w, a1.x, a1.y, a1.z, a1.w};
            float wc[8] = {w0.x, w0.y, w0.z, w0.w, w1.x, w1.y, w1.z, w1.w};
#pragma unroll
            for (int r = 0; r < 8; ++r)
#pragma unroll
                for (int c = 0; c < 8; ++c)
                    acc[r][c] += ar[r] * wc[c];
        }
    }

    float bb[8];
#pragma unroll
    for (int c = 0; c < 4; ++c) {
        bb[c]     = b1[e0 + tx * 4 + c];
        bb[c + 4] = b1[e0 + 64 + tx * 4 + c];
    }
#pragma unroll
    for (int r = 0; r < 8; ++r) {
        float* o = g_Wh + (size_t)(m0 + ty * 8 + r) * 256 + e0;
        float4 v0 = make_float4(acc[r][0] + bb[0], acc[r][1] + bb[1],
                                acc[r][2] + bb[2], acc[r][3] + bb[3]);
        float4 v1 = make_float4(acc[r][4] + bb[4], acc[r][5] + bb[5],
                                acc[r][6] + bb[6], acc[r][7] + bb[7]);
        *(float4*)(o + tx * 4)      = v0;
        *(float4*)(o + 64 + tx * 4) = v1;
    }
}

// ------------------------------------------------------------------
// K3: fused attention. Block = (batch b, 64 query rows). Loop over
// 32-wide j tiles: stage Wh tile + exp-score tile (no max-subtraction
// needed: |s| bounded), outer-product GEMM with fused row-sum, then
// normalize + elu in the epilogue.
// ------------------------------------------------------------------
__global__ void __launch_bounds__(256, 2)
k3_attn(const float* __restrict__ pos, float* __restrict__ out) {
    __shared__ __align__(16) float WhS[32][260];  // [j][d]
    __shared__ __align__(16) float Pt[32][68];    // [j][i]

    const int t  = threadIdx.x;
    const int tx = t & 31;   // d groups: tx*4..+3 and 128+tx*4..+3
    const int ty = t >> 5;   // i group:  ty*8..+7
    const int b  = blockIdx.y;
    const int i0 = blockIdx.x * 64;

    const int ia = t >> 2;   // phase-A: this thread's query row (0..63)
    const int jg = t & 3;    // phase-A: 8-wide j group
    const float el = g_e[(size_t)b * SEQ + i0 + ia];
    const float* __restrict__ erp  = g_e + (size_t)BATCH * SEQ + (size_t)b * SEQ;
    const float* __restrict__ prow = pos + ((size_t)b * SEQ + i0 + ia) * SEQ;
    const float* __restrict__ whb  = g_Wh + (size_t)b * SEQ * DIM;

    const int lj = t >> 3;   // WhS load row (0..31)
    const int lc = t & 7;

    float acc[8][8];
    float psum[8];
#pragma unroll
    for (int r = 0; r < 8; ++r) {
        psum[r] = 0.f;
#pragma unroll
        for (int c = 0; c < 8; ++c) acc[r][c] = 0.f;
    }

    for (int jt = 0; jt < 8; ++jt) {
        const int j0 = jt * 32;
        __syncthreads();  // previous GEMM done reading WhS/Pt

        // stage Wh tile [32][256]
        {
            const float* src = whb + (size_t)(j0 + lj) * DIM + lc * 4;
#pragma unroll
            for (int q = 0; q < 8; ++q)
                *(float4*)&WhS[lj][lc * 4 + q * 32] = *(const float4*)(src + q * 32);
        }
        // stage exp scores: p = exp(leaky(e_l+e_r+a_b) + pos)
        {
#pragma unroll
            for (int q = 0; q < 2; ++q) {
                float4 pv = *(const float4*)(prow + j0 + jg * 8 + q * 4);
                float pa[4] = {pv.x, pv.y, pv.z, pv.w};
#pragma unroll
                for (int i = 0; i < 4; ++i) {
                    const int j = jg * 8 + q * 4 + i;
                    float s0 = el + erp[j0 + j];
                    s0 = (s0 >= 0.f) ? s0 : NEG_SLOPE * s0;
                    Pt[j][ia] = __expf(s0 + pa[i]);
                }
            }
        }
        __syncthreads();

        // outer-product GEMM over this j tile (+ fused row sums)
#pragma unroll 4
        for (int j = 0; j < 32; ++j) {
            float4 p0 = *(const float4*)&Pt[j][ty * 8];
            float4 p1 = *(const float4*)&Pt[j][ty * 8 + 4];
            float4 w0 = *(const float4*)&WhS[j][tx * 4];
            float4 w1 = *(const float4*)&WhS[j][128 + tx * 4];
            float pr[8] = {p0.x, p0.y, p0.z, p0.w, p1.x, p1.y, p1.z, p1.w};
            float wc[8] = {w0.x, w0.y, w0.z, w0.w, w1.x, w1.y, w1.z, w1.w};
#pragma unroll
            for (int r = 0; r < 8; ++r) {
                psum[r] += pr[r];
#pragma unroll
                for (int c = 0; c < 8; ++c) acc[r][c] += pr[r] * wc[c];
            }
        }
    }

    // normalize + elu + store
#pragma unroll
    for (int r = 0; r < 8; ++r) {
        const float inv = 1.f / psum[r];
        float* o = out + ((size_t)b * SEQ + i0 + ty * 8 + r) * DIM;
        float vv[8];
#pragma unroll
        for (int c = 0; c < 8; ++c) {
            float v = acc[r][c] * inv;
            vv[c] = (v > 0.f) ? v : expm1f(v);
        }
        *(float4*)(o + tx * 4)       = make_float4(vv[0], vv[1], vv[2], vv[3]);
        *(float4*)(o + 128 + tx * 4) = make_float4(vv[4], vv[5], vv[6], vv[7]);
    }
}

// ------------------------------------------------------------------
// launcher (graph-capturable: kernel launches only, single stream)
// ------------------------------------------------------------------
extern "C" void kernel_launch(void* const* d_in, const int* in_sizes, int n_in,
                              void* d_out, int out_size) {
    const float* x   = (const float*)d_in[0];
    const float* pos = (const float*)d_in[1];
    const float* W1  = (const float*)d_in[2];
    const float* b1  = (const float*)d_in[3];
    const float* aw  = (const float*)d_in[4];
    const float* ab  = (const float*)d_in[5];
    float* out = (float*)d_out;

    k0_prep<<<1, 256>>>(W1, b1, aw, ab);
    k2_e<<<(BATCH * SEQ) / 8, 256>>>(x);
    k1_gemm<<<dim3(2, (BATCH * SEQ) / 128), 256>>>(x, W1, b1);
    k3_attn<<<dim3(SEQ / 64, BATCH), 256>>>(pos, out);
}

// round 17
// speedup vs baseline: 1.1180x; 1.1180x over previous
#include <cuda_runtime.h>
#include <cuda_bf16.h>
#include <cstdint>

#define BATCH 512
#define SEQ   256
#define DIM   256
#define NEG_SLOPE 0.1f

// ------------------------------------------------------------------
// Scratch (device globals; no allocation inside kernel_launch)
// ------------------------------------------------------------------
__device__ float g_Wh[(size_t)BATCH * SEQ * DIM];   // 134 MB
__device__ float g_e[2 * BATCH * SEQ];              // e_l then e_r
__device__ float g_u[2 * DIM];                      // u_l, u_r = W1^T a_{l,r}
__device__ float g_c[2];                            // b1·a_l , b1·a_r + a_b

// ------------------------------------------------------------------
// Packed fp32x2 helpers (Blackwell FFMA2 — only reachable via PTX)
// ------------------------------------------------------------------
__device__ __forceinline__ void ffma2(unsigned long long& d,
                                      unsigned long long a,
                                      unsigned long long b) {
    asm("fma.rn.f32x2 %0, %1, %2, %0;" : "+l"(d) : "l"(a), "l"(b));
}
__device__ __forceinline__ unsigned long long bcast2(float v) {
    unsigned long long r;
    asm("mov.b64 %0, {%1, %1};" : "=l"(r) : "f"(v));
    return r;
}
__device__ __forceinline__ void unpack2(float& lo, float& hi,
                                        unsigned long long v) {
    asm("mov.b64 {%0, %1}, %2;" : "=f"(lo), "=f"(hi) : "l"(v));
}

// ------------------------------------------------------------------
// K0: u = W1^T a ; c = b1·a (+a_b)
// ------------------------------------------------------------------
__global__ void k0_prep(const float* __restrict__ W1, const float* __restrict__ b1,
                        const float* __restrict__ aw, const float* __restrict__ ab) {
    int d = threadIdx.x;  // 256
    float ul = 0.f, ur = 0.f;
    for (int e = 0; e < DIM; ++e) {
        float w = W1[e * DIM + d];
        ul += w * aw[e];
        ur += w * aw[DIM + e];
    }
    g_u[d] = ul;
    g_u[DIM + d] = ur;

    __shared__ float s1[256], s2[256];
    s1[d] = b1[d] * aw[d];
    s2[d] = b1[d] * aw[DIM + d];
    __syncthreads();
    for (int off = 128; off > 0; off >>= 1) {
        if (d < off) { s1[d] += s1[d + off]; s2[d] += s2[d + off]; }
        __syncthreads();
    }
    if (d == 0) { g_c[0] = s1[0]; g_c[1] = s2[0] + ab[0]; }
}

// ------------------------------------------------------------------
// K2: e_l/e_r = x·u + c  (warp per row)
// ------------------------------------------------------------------
__global__ void k2_e(const float* __restrict__ x) {
    __shared__ __align__(16) float su[2 * DIM];
    int t = threadIdx.x;  // 256
    su[t]       = g_u[t];
    su[t + 256] = g_u[t + 256];
    __syncthreads();

    int warp = t >> 5, lane = t & 31;
    size_t row = (size_t)blockIdx.x * 8 + warp;
    const float4* xr  = reinterpret_cast<const float4*>(x + row * 256);
    const float4* ul4 = reinterpret_cast<const float4*>(su);
    const float4* ur4 = reinterpret_cast<const float4*>(su + 256);

    float el = 0.f, er = 0.f;
#pragma unroll
    for (int k = 0; k < 2; ++k) {
        float4 v = xr[lane + 32 * k];
        float4 a = ul4[lane + 32 * k];
        float4 c = ur4[lane + 32 * k];
        el += v.x * a.x + v.y * a.y + v.z * a.z + v.w * a.w;
        er += v.x * c.x + v.y * c.y + v.z * c.z + v.w * c.w;
    }
#pragma unroll
    for (int o = 16; o > 0; o >>= 1) {
        el += __shfl_down_sync(0xffffffffu, el, o);
        er += __shfl_down_sync(0xffffffffu, er, o);
    }
    if (lane == 0) {
        g_e[row] = el + g_c[0];
        g_e[(size_t)BATCH * SEQ + row] = er + g_c[1];
    }
}

// ------------------------------------------------------------------
// K1: Wh = x @ W1^T + b1  (128x128 block tile, 8x8 microtile, inner
// loop on packed fp32x2: row pairs come free from 128-bit LDS of Xs,
// column operand broadcast-packed once per k-step)
// ------------------------------------------------------------------
__global__ void __launch_bounds__(256, 2)
k1_gemm(const float* __restrict__ x, const float* __restrict__ W1,
        const float* __restrict__ b1) {
    __shared__ __align__(16) float Wt[32][132];  // [k_local][e_local]
    __shared__ __align__(16) float Xs[16][132];  // [k][m]

    const int t  = threadIdx.x;
    const int tx = t & 15;   // column group: cols tx*4..+3 and 64+tx*4..+3
    const int ty = t >> 4;   // row group:    rows ty*8..+7
    const int e0 = blockIdx.x * 128;
    const int m0 = blockIdx.y * 128;

    unsigned long long acc2[4][8];  // [row-pair][col]
#pragma unroll
    for (int rp = 0; rp < 4; ++rp)
#pragma unroll
        for (int c = 0; c < 8; ++c) acc2[rp][c] = 0ull;

    const int we = t >> 1;   // 0..127: e row for W staging
    const int wp = t & 1;
    const int xm = t >> 1;   // 0..127: m row for X staging

    for (int step = 0; step < 16; ++step) {
        __syncthreads();
        if ((step & 1) == 0) {
            const int kc = step >> 1;  // 32-k chunk index
            const float* wsrc = W1 + (size_t)(e0 + we) * 256 + kc * 32;
#pragma unroll
            for (int q = 0; q < 4; ++q) {
                const int d0 = wp * 4 + q * 8;
                float4 v = *(const float4*)(wsrc + d0);
                Wt[d0 + 0][we] = v.x;
                Wt[d0 + 1][we] = v.y;
                Wt[d0 + 2][we] = v.z;
                Wt[d0 + 3][we] = v.w;
            }
        }
        {
            const float* xsrc = x + (size_t)(m0 + xm) * 256 + step * 16 + wp * 8;
            float4 v0 = *(const float4*)(xsrc);
            float4 v1 = *(const float4*)(xsrc + 4);
            const int kb = wp * 8;
            Xs[kb + 0][xm] = v0.x; Xs[kb + 1][xm] = v0.y;
            Xs[kb + 2][xm] = v0.z; Xs[kb + 3][xm] = v0.w;
            Xs[kb + 4][xm] = v1.x; Xs[kb + 5][xm] = v1.y;
            Xs[kb + 6][xm] = v1.z; Xs[kb + 7][xm] = v1.w;
        }
        __syncthreads();

        const int klb = (step & 1) * 16;
#pragma unroll
        for (int kk = 0; kk < 16; ++kk) {
            // row pairs: 2x 128-bit LDS = 4 packed f32x2 operands
            ulonglong2 pa = *(const ulonglong2*)&Xs[kk][ty * 8];
            ulonglong2 pb = *(const ulonglong2*)&Xs[kk][ty * 8 + 4];
            unsigned long long ap[4] = {pa.x, pa.y, pb.x, pb.y};
            float4 w0 = *(const float4*)&Wt[klb + kk][tx * 4];
            float4 w1 = *(const float4*)&Wt[klb + kk][64 + tx * 4];
            unsigned long long wpk[8] = {
                bcast2(w0.x), bcast2(w0.y), bcast2(w0.z), bcast2(w0.w),
                bcast2(w1.x), bcast2(w1.y), bcast2(w1.z), bcast2(w1.w)};
#pragma unroll
            for (int rp = 0; rp < 4; ++rp)
#pragma unroll
                for (int c = 0; c < 8; ++c)
                    ffma2(acc2[rp][c], ap[rp], wpk[c]);
        }
    }

    float bb[8];
#pragma unroll
    for (int c = 0; c < 4; ++c) {
        bb[c]     = b1[e0 + tx * 4 + c];
        bb[c + 4] = b1[e0 + 64 + tx * 4 + c];
    }
#pragma unroll
    for (int rp = 0; rp < 4; ++rp) {
        float flo[8], fhi[8];
#pragma unroll
        for (int c = 0; c < 8; ++c) unpack2(flo[c], fhi[c], acc2[rp][c]);
        float* o0 = g_Wh + (size_t)(m0 + ty * 8 + rp * 2) * 256 + e0;
        float* o1 = o0 + 256;
        *(float4*)(o0 + tx * 4) = make_float4(flo[0] + bb[0], flo[1] + bb[1],
                                              flo[2] + bb[2], flo[3] + bb[3]);
        *(float4*)(o0 + 64 + tx * 4) = make_float4(flo[4] + bb[4], flo[5] + bb[5],
                                                   flo[6] + bb[6], flo[7] + bb[7]);
        *(float4*)(o1 + tx * 4) = make_float4(fhi[0] + bb[0], fhi[1] + bb[1],
                                              fhi[2] + bb[2], fhi[3] + bb[3]);
        *(float4*)(o1 + 64 + tx * 4) = make_float4(fhi[4] + bb[4], fhi[5] + bb[5],
                                                   fhi[6] + bb[6], fhi[7] + bb[7]);
    }
}

// ------------------------------------------------------------------
// K3: fused attention. Packed fp32x2 outer product: i-row pairs come
// free from 128-bit LDS of Pt (contiguous in i); Wh columns broadcast-
// packed per j. Softmax row-sums accumulated in phase-A registers,
// reduced once at the end (out of the hot loop).
// ------------------------------------------------------------------
__global__ void __launch_bounds__(256, 2)
k3_attn(const float* __restrict__ pos, float* __restrict__ out) {
    __shared__ __align__(16) float WhS[32][260];  // [j][d]
    __shared__ __align__(16) float Pt[32][68];    // [j][i]
    __shared__ float psumS[64];

    const int t  = threadIdx.x;
    const int tx = t & 31;   // d groups: tx*4..+3 and 128+tx*4..+3
    const int ty = t >> 5;   // i group:  ty*8..+7
    const int b  = blockIdx.y;
    const int i0 = blockIdx.x * 64;

    const int ia = t >> 2;   // phase-A query row (0..63)
    const int jg = t & 3;    // phase-A 8-wide j group
    const float el = g_e[(size_t)b * SEQ + i0 + ia];
    const float* __restrict__ erp  = g_e + (size_t)BATCH * SEQ + (size_t)b * SEQ;
    const float* __restrict__ prow = pos + ((size_t)b * SEQ + i0 + ia) * SEQ;
    const float* __restrict__ whb  = g_Wh + (size_t)b * SEQ * DIM;

    const int lj = t >> 3;   // WhS load row (0..31)
    const int lc = t & 7;

    unsigned long long acc2[4][8];  // [i-pair][d-col]
#pragma unroll
    for (int rp = 0; rp < 4; ++rp)
#pragma unroll
        for (int c = 0; c < 8; ++c) acc2[rp][c] = 0ull;
    float rowsum = 0.f;      // phase-A partial softmax denominator

    for (int jt = 0; jt < 8; ++jt) {
        const int j0 = jt * 32;
        __syncthreads();  // previous GEMM done reading WhS/Pt

        // stage Wh tile [32][256]
        {
            const float* src = whb + (size_t)(j0 + lj) * DIM + lc * 4;
#pragma unroll
            for (int q = 0; q < 8; ++q)
                *(float4*)&WhS[lj][lc * 4 + q * 32] = *(const float4*)(src + q * 32);
        }
        // stage exp scores: p = exp(leaky(e_l+e_r+a_b) + pos); accumulate row sums
        {
#pragma unroll
            for (int q = 0; q < 2; ++q) {
                float4 pv = *(const float4*)(prow + j0 + jg * 8 + q * 4);
                float pa[4] = {pv.x, pv.y, pv.z, pv.w};
#pragma unroll
                for (int i = 0; i < 4; ++i) {
                    const int j = jg * 8 + q * 4 + i;
                    float s0 = el + erp[j0 + j];
                    s0 = (s0 >= 0.f) ? s0 : NEG_SLOPE * s0;
                    float pe = __expf(s0 + pa[i]);
                    Pt[j][ia] = pe;
                    rowsum += pe;
                }
            }
        }
        __syncthreads();

        // packed outer-product GEMM over this j tile
#pragma unroll 4
        for (int j = 0; j < 32; ++j) {
            ulonglong2 pa = *(const ulonglong2*)&Pt[j][ty * 8];
            ulonglong2 pb = *(const ulonglong2*)&Pt[j][ty * 8 + 4];
            unsigned long long ap[4] = {pa.x, pa.y, pb.x, pb.y};
            float4 w0 = *(const float4*)&WhS[j][tx * 4];
            float4 w1 = *(const float4*)&WhS[j][128 + tx * 4];
            unsigned long long wpk[8] = {
                bcast2(w0.x), bcast2(w0.y), bcast2(w0.z), bcast2(w0.w),
                bcast2(w1.x), bcast2(w1.y), bcast2(w1.z), bcast2(w1.w)};
#pragma unroll
            for (int rp = 0; rp < 4; ++rp)
#pragma unroll
                for (int c = 0; c < 8; ++c)
                    ffma2(acc2[rp][c], ap[rp], wpk[c]);
        }
    }

    // finish softmax denominators: reduce across the 4 jg lanes per row
    rowsum += __shfl_xor_sync(0xffffffffu, rowsum, 1);
    rowsum += __shfl_xor_sync(0xffffffffu, rowsum, 2);
    if (jg == 0) psumS[ia] = rowsum;
    __syncthreads();

    // normalize + elu + store
#pragma unroll
    for (int rp = 0; rp < 4; ++rp) {
        float flo[8], fhi[8];
#pragma unroll
        for (int c = 0; c < 8; ++c) unpack2(flo[c], fhi[c], acc2[rp][c]);
#pragma unroll
        for (int h = 0; h < 2; ++h) {
            const int r = rp * 2 + h;
            const float inv = 1.f / psumS[ty * 8 + r];
            const float* f = h ? fhi : flo;
            float* o = out + ((size_t)b * SEQ + i0 + ty * 8 + r) * DIM;
            float vv[8];
#pragma unroll
            for (int c = 0; c < 8; ++c) {
                float v = f[c] * inv;
                vv[c] = (v > 0.f) ? v : expm1f(v);
            }
            *(float4*)(o + tx * 4)       = make_float4(vv[0], vv[1], vv[2], vv[3]);
            *(float4*)(o + 128 + tx * 4) = make_float4(vv[4], vv[5], vv[6], vv[7]);
        }
    }
}

// ------------------------------------------------------------------
// launcher (graph-capturable: kernel launches only, single stream)
// ------------------------------------------------------------------
extern "C" void kernel_launch(void* const* d_in, const int* in_sizes, int n_in,
                              void* d_out, int out_size) {
    const float* x   = (const float*)d_in[0];
    const float* pos = (const float*)d_in[1];
    const float* W1  = (const float*)d_in[2];
    const float* b1  = (const float*)d_in[3];
    const float* aw  = (const float*)d_in[4];
    const float* ab  = (const float*)d_in[5];
    float* out = (float*)d_out;

    k0_prep<<<1, 256>>>(W1, b1, aw, ab);
    k2_e<<<(BATCH * SEQ) / 8, 256>>>(x);
    k1_gemm<<<dim3(2, (BATCH * SEQ) / 128), 256>>>(x, W1, b1);
    k3_attn<<<dim3(SEQ / 64, BATCH), 256>>>(pos, out);
}